// round 4
// baseline (speedup 1.0000x reference)
#include <cuda_runtime.h>
#include <math.h>

// Shapes (hardcoded from reference): B=16, N=32, C=8, O=16
// d_in order: x0, x1, x2, x3, W0, b0, W1, b1, W2, b2, W3, b3
// d_out: concat(out0[16,16], out1[16,32,16], out2[16,32,32,16], out3[16,32,32,32,16])

#define NB 16
#define NN 32
#define NC 8
#define NO 16

// Scratch (device globals — no runtime allocation)
__device__ float g_R3[NB * NN * NN * 16];   // reduce(x3): [b,a1,a2][max8|min8]
__device__ float g_T45[NB * NN * NN * 16];  // b3 + x2[b,j,k]·W3_p4 + x2[b,k,j]·W3_p5

__device__ __forceinline__ float sigm(float x) {
    return 1.0f / (1.0f + __expf(-x));
}

// ---------------------------------------------------------------------------
// Prep: R3 reduction table + T45 x2-pair table
// grid 576 x 256: blocks [0,512) -> R3 (131072 threads: b,i,j,c)
//                 blocks [512,576) -> T45 (16384 threads: b,j,k)
// ---------------------------------------------------------------------------
__global__ void __launch_bounds__(256) k_prep(
    const float* __restrict__ x2, const float* __restrict__ x3,
    const float* __restrict__ W3, const float* __restrict__ b3)
{
    int blk = blockIdx.x, tid = threadIdx.x;
    if (blk < 512) {
        int t = blk * 256 + tid;            // b,i,j,c
        int c = t & 7, j = (t >> 3) & 31, i = (t >> 8) & 31, b = t >> 13;
        // reduce(x3)[b,i,j,c] = max/min over a3 of x3[b,i,j,a3,c], excluding a3==j
        const float* p = x3 + (((((b * 32 + i) * 32 + j) * 32) * 8) + c);
        float vmax = -INFINITY, vmin = INFINITY;
        #pragma unroll 8
        for (int a = 0; a < 32; a++) {
            float v = p[a * 8];
            float vm = (a == j) ? 0.0f : v;   // mask: x*m -> 0 in max
            float vn = (a == j) ? 1.0f : v;   // mask: x*m+(1-m) -> 1 in min
            vmax = fmaxf(vmax, vm);
            vmin = fminf(vmin, vn);
        }
        int o = ((b * 32 + i) * 32 + j) * 16;
        g_R3[o + c] = vmax;
        g_R3[o + 8 + c] = vmin;
    } else {
        int t = (blk - 512) * 256 + tid;    // b,j,k
        int k = t & 31, j = (t >> 5) & 31, b = t >> 10;
        const float* pjk = x2 + ((b * 32 + j) * 32 + k) * 8;
        const float* pkj = x2 + ((b * 32 + k) * 32 + j) * 8;
        float acc[16];
        #pragma unroll
        for (int o = 0; o < 16; o++) acc[o] = b3[o];
        #pragma unroll
        for (int c = 0; c < 8; c++) {
            float v4 = pjk[c], v5 = pkj[c];
            #pragma unroll
            for (int o = 0; o < 16; o++)
                acc[o] += v4 * W3[(64 + c) * 16 + o] + v5 * W3[(80 + c) * 16 + o];
        }
        float4* dst = (float4*)(g_T45 + (size_t)t * 16);
        dst[0] = make_float4(acc[0], acc[1], acc[2], acc[3]);
        dst[1] = make_float4(acc[4], acc[5], acc[6], acc[7]);
        dst[2] = make_float4(acc[8], acc[9], acc[10], acc[11]);
        dst[3] = make_float4(acc[12], acc[13], acc[14], acc[15]);
    }
}

// ---------------------------------------------------------------------------
// Main: out3. grid = B*N*2 = 1024 blocks, 256 threads.
// block -> (b, i, half h of j-range). thread -> (jb = tid>>5, k = tid&31),
// handles j = h*16 + jb*2 + {0,1}  (G=2 position blocking for weight reuse).
// logit = T45[b,j,k] + a[j] + c[k] + Σ_{6 terms} x3[perm]·Wterm
// ---------------------------------------------------------------------------
__global__ void __launch_bounds__(256) k_main(
    const float* __restrict__ x2, const float* __restrict__ x3,
    const float* __restrict__ W3, float* __restrict__ out3)
{
    __shared__ __align__(16) float sW[6 * 8 * 16];  // x3-part weights, [term][c][o]
    __shared__ __align__(16) float sA[32 * 16];     // a[j][o]: p0 + p2 x2-terms
    __shared__ __align__(16) float sC[32 * 16];     // c[k][o]: p1 + p3 x2-terms

    int blk = blockIdx.x;
    int b = blk >> 6;
    int i = (blk >> 1) & 31;
    int h = blk & 1;
    int tid = threadIdx.x;

    // stage x3-part weight blocks: rows 16*term+8+c of W3
    for (int idx = tid; idx < 768; idx += 256) {
        int term = idx >> 7;
        int r = idx & 127;
        int cc = r >> 4, o = r & 15;
        sW[idx] = W3[(16 * term + 8 + cc) * 16 + o];
    }
    // per-CTA x2-pair vectors a[j], c[k]
    const float* x2b = x2 + (size_t)b * 32 * 32 * 8;
    for (int idx = tid; idx < 512; idx += 256) {
        int j = idx >> 4, o = idx & 15;
        float accA = 0.0f, accC = 0.0f;
        #pragma unroll
        for (int cc = 0; cc < 8; cc++) {
            float xij = x2b[(i * 32 + j) * 8 + cc];
            float xji = x2b[(j * 32 + i) * 8 + cc];
            accA += xij * W3[cc * 16 + o] + xji * W3[(32 + cc) * 16 + o];
            accC += xij * W3[(16 + cc) * 16 + o] + xji * W3[(48 + cc) * 16 + o];
        }
        sA[idx] = accA;
        sC[idx] = accC;
    }
    __syncthreads();

    int jb = tid >> 5, k = tid & 31;
    int j0 = h * 16 + jb * 2;
    const float* x3b = x3 + (size_t)b * 32 * 32 * 32 * 8;

    // accumulators init: T45 + a + c
    float acc[2][16];
    #pragma unroll
    for (int g = 0; g < 2; g++) {
        int j = j0 + g;
        const float4* t45 = (const float4*)(g_T45 + (((size_t)b * 32 + j) * 32 + k) * 16);
        const float4* pa = (const float4*)(sA + j * 16);
        const float4* pc = (const float4*)(sC + k * 16);
        #pragma unroll
        for (int q = 0; q < 4; q++) {
            float4 t = t45[q], a4 = pa[q], c4 = pc[q];
            acc[g][q * 4 + 0] = t.x + a4.x + c4.x;
            acc[g][q * 4 + 1] = t.y + a4.y + c4.y;
            acc[g][q * 4 + 2] = t.z + a4.z + c4.z;
            acc[g][q * 4 + 3] = t.w + a4.w + c4.w;
        }
    }

    // gather offsets (floats): x3[b,a1,a2,a3,c] -> a1*8192 + a2*256 + a3*8
    int iS1 = i * 8192, iS2 = i * 256, iS3 = i * 8;
    int kS1 = k * 8192, kS2 = k * 256, kS3 = k * 8;
    int offs[2][6];
    #pragma unroll
    for (int g = 0; g < 2; g++) {
        int j = j0 + g;
        int jS1 = j * 8192, jS2 = j * 256, jS3 = j * 8;
        offs[g][0] = iS1 + jS2 + kS3;  // x3[b,i,j,k]  rows  8..15
        offs[g][1] = iS1 + kS2 + jS3;  // x3[b,i,k,j]  rows 24..31
        offs[g][2] = jS1 + iS2 + kS3;  // x3[b,j,i,k]  rows 40..47
        offs[g][3] = kS1 + iS2 + jS3;  // x3[b,k,i,j]  rows 56..63
        offs[g][4] = jS1 + kS2 + iS3;  // x3[b,j,k,i]  rows 72..79
        offs[g][5] = kS1 + jS2 + iS3;  // x3[b,k,j,i]  rows 88..95
    }

    #pragma unroll
    for (int term = 0; term < 6; term++) {
        float v[2][8];
        #pragma unroll
        for (int g = 0; g < 2; g++) {
            const float* p = x3b + offs[g][term];
            float4 lo = *(const float4*)p;
            float4 hi = *(const float4*)(p + 4);
            v[g][0] = lo.x; v[g][1] = lo.y; v[g][2] = lo.z; v[g][3] = lo.w;
            v[g][4] = hi.x; v[g][5] = hi.y; v[g][6] = hi.z; v[g][7] = hi.w;
        }
        const float* wt = sW + term * 128;
        #pragma unroll
        for (int cc = 0; cc < 8; cc++) {
            float4 w0 = *(const float4*)(wt + cc * 16);
            float4 w1 = *(const float4*)(wt + cc * 16 + 4);
            float4 w2 = *(const float4*)(wt + cc * 16 + 8);
            float4 w3 = *(const float4*)(wt + cc * 16 + 12);
            #pragma unroll
            for (int g = 0; g < 2; g++) {
                float s = v[g][cc];
                acc[g][0]  += s * w0.x; acc[g][1]  += s * w0.y;
                acc[g][2]  += s * w0.z; acc[g][3]  += s * w0.w;
                acc[g][4]  += s * w1.x; acc[g][5]  += s * w1.y;
                acc[g][6]  += s * w1.z; acc[g][7]  += s * w1.w;
                acc[g][8]  += s * w2.x; acc[g][9]  += s * w2.y;
                acc[g][10] += s * w2.z; acc[g][11] += s * w2.w;
                acc[g][12] += s * w3.x; acc[g][13] += s * w3.y;
                acc[g][14] += s * w3.z; acc[g][15] += s * w3.w;
            }
        }
    }

    // sigmoid + store
    #pragma unroll
    for (int g = 0; g < 2; g++) {
        int j = j0 + g;
        float4* dst = (float4*)(out3 + ((((size_t)b * 32 + i) * 32 + j) * 32 + k) * 16);
        #pragma unroll
        for (int q = 0; q < 4; q++) {
            float4 r;
            r.x = sigm(acc[g][q * 4 + 0]);
            r.y = sigm(acc[g][q * 4 + 1]);
            r.z = sigm(acc[g][q * 4 + 2]);
            r.w = sigm(acc[g][q * 4 + 3]);
            dst[q] = r;
        }
    }
}

// ---------------------------------------------------------------------------
// Tail: out2 (blocks 0..63), out1 (64..65), out0 (66)
// ---------------------------------------------------------------------------
__global__ void __launch_bounds__(256) k_tail(
    const float* __restrict__ x0, const float* __restrict__ x1,
    const float* __restrict__ x2,
    const float* __restrict__ W0, const float* __restrict__ b0,
    const float* __restrict__ W1, const float* __restrict__ b1,
    const float* __restrict__ W2, const float* __restrict__ b2,
    float* __restrict__ out0, float* __restrict__ out1, float* __restrict__ out2)
{
    int blk = blockIdx.x, tid = threadIdx.x;
    if (blk < 64) {
        // out2: thread per (b,i,j), 16 outputs, 64-ch f2
        __shared__ __align__(16) float sW2[64 * 16];
        for (int idx = tid; idx < 1024; idx += 256) sW2[idx] = W2[idx];
        __syncthreads();

        int idx = blk * 256 + tid;  // b,i,j
        int j = idx & 31, i = (idx >> 5) & 31, b = idx >> 10;
        float f[64];
        const float* x1i = x1 + (b * 32 + i) * 8;
        const float* x1j = x1 + (b * 32 + j) * 8;
        const float* x2ij = x2 + ((b * 32 + i) * 32 + j) * 8;
        const float* x2ji = x2 + ((b * 32 + j) * 32 + i) * 8;
        const float* r3ij = g_R3 + ((b * 32 + i) * 32 + j) * 16;
        const float* r3ji = g_R3 + ((b * 32 + j) * 32 + i) * 16;
        #pragma unroll
        for (int c = 0; c < 8; c++) {
            f[c] = x1i[c];
            f[8 + c] = x2ij[c];
            f[32 + c] = x1j[c];
            f[40 + c] = x2ji[c];
        }
        #pragma unroll
        for (int c = 0; c < 16; c++) {
            f[16 + c] = r3ij[c];
            f[48 + c] = r3ji[c];
        }
        float acc[16];
        #pragma unroll
        for (int o = 0; o < 16; o++) acc[o] = b2[o];
        #pragma unroll
        for (int r = 0; r < 64; r++) {
            float4 w0 = *(const float4*)(sW2 + r * 16);
            float4 w1 = *(const float4*)(sW2 + r * 16 + 4);
            float4 w2 = *(const float4*)(sW2 + r * 16 + 8);
            float4 w3 = *(const float4*)(sW2 + r * 16 + 12);
            float s = f[r];
            acc[0]  += s * w0.x; acc[1]  += s * w0.y; acc[2]  += s * w0.z; acc[3]  += s * w0.w;
            acc[4]  += s * w1.x; acc[5]  += s * w1.y; acc[6]  += s * w1.z; acc[7]  += s * w1.w;
            acc[8]  += s * w2.x; acc[9]  += s * w2.y; acc[10] += s * w2.z; acc[11] += s * w2.w;
            acc[12] += s * w3.x; acc[13] += s * w3.y; acc[14] += s * w3.z; acc[15] += s * w3.w;
        }
        float* dst = out2 + (size_t)idx * 16;
        #pragma unroll
        for (int o = 0; o < 16; o++) dst[o] = sigm(acc[o]);
    } else if (blk < 66) {
        // out1: thread per (b,i), 16 outputs, 32-ch f1
        int idx = (blk - 64) * 256 + tid;
        if (idx < 512) {
            int b = idx >> 5, i = idx & 31;
            float f[32];
            #pragma unroll
            for (int c = 0; c < 8; c++) {
                f[c] = x0[b * 8 + c];
                f[8 + c] = x1[(b * 32 + i) * 8 + c];
            }
            // reduce(x2)[b,i]: max/min over SECOND object axis a (axis=-2),
            // i.e. x2[b,i,a,c], with a==i masked -> 0 (max) / 1 (min)
            #pragma unroll
            for (int c = 0; c < 8; c++) {
                float vmax = -INFINITY, vmin = INFINITY;
                for (int a = 0; a < 32; a++) {
                    float v = x2[((b * 32 + i) * 32 + a) * 8 + c];
                    float vm = (a == i) ? 0.0f : v;
                    float vn = (a == i) ? 1.0f : v;
                    vmax = fmaxf(vmax, vm);
                    vmin = fminf(vmin, vn);
                }
                f[16 + c] = vmax;
                f[24 + c] = vmin;
            }
            float acc[16];
            #pragma unroll
            for (int o = 0; o < 16; o++) acc[o] = b1[o];
            #pragma unroll
            for (int r = 0; r < 32; r++) {
                float s = f[r];
                #pragma unroll
                for (int o = 0; o < 16; o++) acc[o] += s * W1[r * 16 + o];
            }
            float* dst = out1 + (size_t)idx * 16;
            #pragma unroll
            for (int o = 0; o < 16; o++) dst[o] = sigm(acc[o]);
        }
    } else {
        // out0: thread per (b,o)
        int b = tid >> 4, o = tid & 15;
        float f[24];
        #pragma unroll
        for (int c = 0; c < 8; c++) f[c] = x0[b * 8 + c];
        // reduce(x1): plain max/min over N (no exclusion — ndim < 4 branch)
        #pragma unroll
        for (int c = 0; c < 8; c++) {
            float vmax = -INFINITY, vmin = INFINITY;
            for (int n = 0; n < 32; n++) {
                float v = x1[(b * 32 + n) * 8 + c];
                vmax = fmaxf(vmax, v);
                vmin = fminf(vmin, v);
            }
            f[8 + c] = vmax;
            f[16 + c] = vmin;
        }
        float acc = b0[o];
        #pragma unroll
        for (int r = 0; r < 24; r++) acc += f[r] * W0[r * 16 + o];
        out0[b * 16 + o] = sigm(acc);
    }
}

// ---------------------------------------------------------------------------
extern "C" void kernel_launch(void* const* d_in, const int* in_sizes, int n_in,
                              void* d_out, int out_size)
{
    const float* x0 = (const float*)d_in[0];
    const float* x1 = (const float*)d_in[1];
    const float* x2 = (const float*)d_in[2];
    const float* x3 = (const float*)d_in[3];
    const float* W0 = (const float*)d_in[4];
    const float* b0 = (const float*)d_in[5];
    const float* W1 = (const float*)d_in[6];
    const float* b1 = (const float*)d_in[7];
    const float* W2 = (const float*)d_in[8];
    const float* b2 = (const float*)d_in[9];
    const float* W3 = (const float*)d_in[10];
    const float* b3 = (const float*)d_in[11];

    float* out = (float*)d_out;
    float* out0 = out;                 // [16,16]            =     256
    float* out1 = out + 256;           // [16,32,16]         =    8192
    float* out2 = out + 8448;          // [16,32,32,16]      =  262144
    float* out3 = out + 270592;        // [16,32,32,32,16]   = 8388608

    k_prep<<<576, 256>>>(x2, x3, W3, b3);
    k_main<<<1024, 256>>>(x2, x3, W3, out3);
    k_tail<<<67, 256>>>(x0, x1, x2, W0, b0, W1, b1, W2, b2, out0, out1, out2);
}